// round 12
// baseline (speedup 1.0000x reference)
#include <cuda_runtime.h>
#include <cuda_bf16.h>
#include <cuda_fp16.h>
#include <cstdint>

#define N_TOK 8192
#define DIM   64
#define BM    64
#define BN    128
#define HALF_KV 4096
#define NITER (HALF_KV / BN)   // 32

// ---------------- global scratch ----------------
__device__ __nv_bfloat16 g_Qh[N_TOK * DIM], g_Ql[N_TOK * DIM];
__device__ __nv_bfloat16 g_Kh[N_TOK * DIM], g_Kl[N_TOK * DIM];
__device__ __half g_Xt[DIM * N_TOK];
__device__ float g_Opart[2][N_TOK * DIM];
__device__ float g_mpart[2][N_TOK];
__device__ float g_lpart[2][N_TOK];

// ---------------- helpers ----------------
__device__ __forceinline__ uint32_t smem_u32(const void* p) {
    uint32_t a;
    asm("{ .reg .u64 t; cvta.to.shared.u64 t, %1; cvt.u32.u64 %0, t; }" : "=r"(a) : "l"(p));
    return a;
}
__device__ __forceinline__ uint32_t swz8(uint32_t row, uint32_t ch) {
    return row * 128u + ((ch ^ (row & 7u)) << 4);
}
__device__ __forceinline__ uint32_t swz16(uint32_t row, uint32_t ch) {
    return row * 256u + ((ch ^ (row & 7u)) << 4);
}
__device__ __forceinline__ void ldsm4(uint32_t& r0, uint32_t& r1, uint32_t& r2,
                                      uint32_t& r3, uint32_t addr) {
    asm volatile("ldmatrix.sync.aligned.m8n8.x4.shared.b16 {%0,%1,%2,%3}, [%4];"
                 : "=r"(r0), "=r"(r1), "=r"(r2), "=r"(r3) : "r"(addr));
}
__device__ __forceinline__ void mma16816(float* c, const uint32_t* a, uint32_t b0,
                                         uint32_t b1) {
    asm volatile(
        "mma.sync.aligned.m16n8k16.row.col.f32.bf16.bf16.f32 "
        "{%0,%1,%2,%3}, {%4,%5,%6,%7}, {%8,%9}, {%0,%1,%2,%3};"
        : "+f"(c[0]), "+f"(c[1]), "+f"(c[2]), "+f"(c[3])
        : "r"(a[0]), "r"(a[1]), "r"(a[2]), "r"(a[3]), "r"(b0), "r"(b1));
}
__device__ __forceinline__ void mma16816h(float* c, const uint32_t* a, uint32_t b0,
                                          uint32_t b1) {
    asm volatile(
        "mma.sync.aligned.m16n8k16.row.col.f32.f16.f16.f32 "
        "{%0,%1,%2,%3}, {%4,%5,%6,%7}, {%8,%9}, {%0,%1,%2,%3};"
        : "+f"(c[0]), "+f"(c[1]), "+f"(c[2]), "+f"(c[3])
        : "r"(a[0]), "r"(a[1]), "r"(a[2]), "r"(a[3]), "r"(b0), "r"(b1));
}
__device__ __forceinline__ uint32_t cvt2h(float lo, float hi) {
    uint32_t r;
    asm("cvt.rn.f16x2.f32 %0, %1, %2;" : "=r"(r) : "f"(hi), "f"(lo));
    return r;
}
__device__ __forceinline__ void cpa16(uint32_t dst, const void* src) {
    asm volatile("cp.async.cg.shared.global [%0], [%1], 16;" :: "r"(dst), "l"(src));
}
#define CP_COMMIT() asm volatile("cp.async.commit_group;" ::: "memory")
#define CP_WAIT(n)  asm volatile("cp.async.wait_group %0;" :: "n"(n) : "memory")

// ---------------- projection + split kernel (512 blocks x 16 rows) ----------------
__global__ __launch_bounds__(256) void proj_kernel(const float* __restrict__ x,
                                                   const float* __restrict__ R,
                                                   const float* __restrict__ E) {
    extern __shared__ float psm[];
    float* Rs = psm;                 // 4096
    float* Es = psm + 4096;          // 4096
    float* xs = psm + 8192;          // 16*65 padded
    int tid = threadIdx.x;
    int row0 = blockIdx.x * 16;
    {
        const float4* Rsrc = (const float4*)R;
        const float4* Esrc = (const float4*)E;
        float4* Rd = (float4*)Rs;
        float4* Ed = (float4*)Es;
#pragma unroll
        for (int i = tid; i < 1024; i += 256) { Rd[i] = Rsrc[i]; Ed[i] = Esrc[i]; }
    }
#pragma unroll
    for (int i = tid; i < 1024; i += 256) {
        int row = i >> 6, c = i & 63;
        xs[row * 65 + c] = x[(size_t)(row0 + row) * 64 + c];
    }
    __syncthreads();

    // coalesced transposed fp16 store of x
#pragma unroll
    for (int i = tid; i < 1024; i += 256) {
        int d = i >> 4, row = i & 15;
        g_Xt[(size_t)d * N_TOK + row0 + row] = __float2half_rn(xs[row * 65 + d]);
    }

    int ty = tid >> 6, col = tid & 63;   // 4 rows per thread
    float aq[4], ak[4];
#pragma unroll
    for (int r = 0; r < 4; r++) { aq[r] = 0.f; ak[r] = 0.f; }
#pragma unroll 8
    for (int k = 0; k < 64; k++) {
        float rv = Rs[k * 64 + col];
        float ev = Es[k * 64 + col];
#pragma unroll
        for (int r = 0; r < 4; r++) {
            float xv = xs[(r * 4 + ty) * 65 + k];
            aq[r] = fmaf(xv, rv, aq[r]);
            ak[r] = fmaf(xv, ev, ak[r]);
        }
    }
#pragma unroll
    for (int r = 0; r < 4; r++) {
        int row = row0 + r * 4 + ty;
        float q = aq[r] * 0.125f;
        __nv_bfloat16 qh = __float2bfloat16(q);
        g_Qh[(size_t)row * 64 + col] = qh;
        g_Ql[(size_t)row * 64 + col] = __float2bfloat16(q - __bfloat162float(qh));
        __nv_bfloat16 kh = __float2bfloat16(ak[r]);
        g_Kh[(size_t)row * 64 + col] = kh;
        g_Kl[(size_t)row * 64 + col] = __float2bfloat16(ak[r] - __bfloat162float(kh));
    }
}
#define PROJ_SMEM ((4096 + 4096 + 16 * 65) * 4)

// ---------------- fused flash attention (HMMA, K+X double-buffered, 1 group/iter) ----------------
#define OFF_KH0 0
#define OFF_KL0 16384
#define OFF_KH1 32768
#define OFF_KL1 49152
#define OFF_X0  65536
#define OFF_X1  81920
#define SMEM_TOTAL 98304

__global__ __launch_bounds__(128, 2) void attn_kernel() {
    extern __shared__ char sm[];
    uint32_t sb = smem_u32(sm);
    const int tid = threadIdx.x;
    const int lane = tid & 31;
    const int w = tid >> 5;
    const int m0 = w * 16;
    const int rb = blockIdx.x >> 1;
    const int half = blockIdx.x & 1;
    const int row0 = rb * BM;
    const int jb0 = half * HALF_KV;
    const int g = lane >> 3, rr = lane & 7;

    // ---- stage Q (hi/lo) into X smem region, build A-fragments once ----
#pragma unroll
    for (int i = tid; i < 64 * 8; i += 128) {
        int row = i >> 3, ch = i & 7;
        uint32_t sw = swz8(row, ch);
        *(uint4*)(sm + OFF_X0 + sw) = *(const uint4*)(g_Qh + (size_t)(row0 + row) * DIM + ch * 8);
        *(uint4*)(sm + OFF_X1 + sw) = *(const uint4*)(g_Ql + (size_t)(row0 + row) * DIM + ch * 8);
    }
    __syncthreads();

    uint32_t qh[4][4], ql[4][4];
    {
        int arow = m0 + ((g & 1) << 3) + rr;
#pragma unroll
        for (int ks = 0; ks < 4; ks++) {
            uint32_t off = swz8(arow, ks * 2 + (g >> 1));
            ldsm4(qh[ks][0], qh[ks][1], qh[ks][2], qh[ks][3], sb + OFF_X0 + off);
            ldsm4(ql[ks][0], ql[ks][1], ql[ks][2], ql[ks][3], sb + OFF_X1 + off);
        }
    }
    __syncthreads();   // Q frags built; X regions reusable

    // ---- prologue: issue {K,X}(0) then {K,X}(1) as two groups ----
#pragma unroll
    for (int pre = 0; pre < 2; pre++) {
        int jp = jb0 + pre * BN;
        uint32_t kb_h = pre ? OFF_KH1 : OFF_KH0;
        uint32_t kb_l = pre ? OFF_KL1 : OFF_KL0;
        uint32_t xb   = pre ? OFF_X1  : OFF_X0;
#pragma unroll
        for (int i = tid; i < 128 * 8; i += 128) {
            int row = i >> 3, ch = i & 7;
            uint32_t sw = swz8(row, ch);
            cpa16(sb + kb_h + sw, g_Kh + (size_t)(jp + row) * DIM + ch * 8);
            cpa16(sb + kb_l + sw, g_Kl + (size_t)(jp + row) * DIM + ch * 8);
        }
#pragma unroll
        for (int i = tid; i < 64 * 16; i += 128) {
            int row = i >> 4, ch = i & 15;
            uint32_t sw = swz16(row, ch);
            cpa16(sb + xb + sw, g_Xt + (size_t)row * N_TOK + jp + ch * 8);
        }
        CP_COMMIT();
    }

    float o[8][4];
#pragma unroll
    for (int t = 0; t < 8; t++)
#pragma unroll
        for (int j = 0; j < 4; j++) o[t][j] = 0.f;
    float mc0 = -3.0e38f, mc1 = -3.0e38f, lc0 = 0.f, lc1 = 0.f;

    for (int it = 0; it < NITER; it++) {
        uint32_t kh_b = (it & 1) ? OFF_KH1 : OFF_KH0;
        uint32_t kl_b = (it & 1) ? OFF_KL1 : OFF_KL0;
        uint32_t x_b  = (it & 1) ? OFF_X1  : OFF_X0;

        if (it + 2 < NITER) {
            // ---- issue {K,X}(it+2) into the buffers freed after iter it ----
            // (safe: all warps finished iter it's reads of buf[it&1]... issued
            //  AFTER the barrier below which confirms iter it-1 fully done;
            //  buf[(it+2)&1] == buf[it&1] is still being read THIS iter, so
            //  the issue must come after this iter's reads. We issue at the
            //  BOTTOM of the loop instead — see below.)
            ;
        }
        // wait: groups outstanding = (it+1 issued? ) ... exactly one newer
        // group may be pending (issued at bottom of previous iter or prologue).
        if (it + 1 < NITER) { CP_WAIT(1); } else { CP_WAIT(0); }
        __syncthreads();   // {K,X}(it) visible to all warps

        // ---- GEMM1: S = Qh*Kh + Qh*Kl + Ql*Kh (bf16 3-pass) ----
        float s[16][4];
#pragma unroll
        for (int t = 0; t < 16; t++)
#pragma unroll
            for (int j = 0; j < 4; j++) s[t][j] = 0.f;
#pragma unroll
        for (int np = 0; np < 8; np++) {
            int brow = np * 16 + ((g >> 1) << 3) + rr;
#pragma unroll
            for (int ks = 0; ks < 4; ks++) {
                uint32_t off = swz8(brow, ks * 2 + (g & 1));
                uint32_t b0, b1, b2, b3, c0, c1, c2, c3;
                ldsm4(b0, b1, b2, b3, sb + kh_b + off);
                ldsm4(c0, c1, c2, c3, sb + kl_b + off);
                mma16816(s[2 * np],     qh[ks], b0, b1);
                mma16816(s[2 * np + 1], qh[ks], b2, b3);
                mma16816(s[2 * np],     qh[ks], c0, c1);
                mma16816(s[2 * np + 1], qh[ks], c2, c3);
                mma16816(s[2 * np],     ql[ks], b0, b1);
                mma16816(s[2 * np + 1], ql[ks], b2, b3);
            }
        }

        // ---- row max ----
        float mx0 = -3.0e38f, mx1 = -3.0e38f;
#pragma unroll
        for (int t = 0; t < 16; t++) {
            mx0 = fmaxf(mx0, fmaxf(s[t][0], s[t][1]));
            mx1 = fmaxf(mx1, fmaxf(s[t][2], s[t][3]));
        }
        mx0 = fmaxf(mx0, __shfl_xor_sync(0xffffffffu, mx0, 1));
        mx0 = fmaxf(mx0, __shfl_xor_sync(0xffffffffu, mx0, 2));
        mx1 = fmaxf(mx1, __shfl_xor_sync(0xffffffffu, mx1, 1));
        mx1 = fmaxf(mx1, __shfl_xor_sync(0xffffffffu, mx1, 2));
        float mn0 = fmaxf(mc0, mx0), mn1 = fmaxf(mc1, mx1);
        float sc0 = __expf(mc0 - mn0), sc1 = __expf(mc1 - mn1);
        mc0 = mn0; mc1 = mn1;

        // ---- rescale O ----
#pragma unroll
        for (int t = 0; t < 8; t++) {
            o[t][0] *= sc0; o[t][1] *= sc0;
            o[t][2] *= sc1; o[t][3] *= sc1;
        }

        // ---- interleaved: exp/cvt chunk kt, then its fp16 GEMM2 MMAs ----
        float rs0 = 0.f, rs1 = 0.f;
#pragma unroll
        for (int kt = 0; kt < 8; kt++) {
            float p0 = __expf(s[2 * kt][0] - mn0);
            float p1 = __expf(s[2 * kt][1] - mn0);
            float p2 = __expf(s[2 * kt][2] - mn1);
            float p3 = __expf(s[2 * kt][3] - mn1);
            float p4 = __expf(s[2 * kt + 1][0] - mn0);
            float p5 = __expf(s[2 * kt + 1][1] - mn0);
            float p6 = __expf(s[2 * kt + 1][2] - mn1);
            float p7 = __expf(s[2 * kt + 1][3] - mn1);
            rs0 += (p0 + p1) + (p4 + p5);
            rs1 += (p2 + p3) + (p6 + p7);
            uint32_t pa[4];
            pa[0] = cvt2h(p0, p1);
            pa[1] = cvt2h(p2, p3);
            pa[2] = cvt2h(p4, p5);
            pa[3] = cvt2h(p6, p7);
#pragma unroll
            for (int np = 0; np < 4; np++) {
                int brow = np * 16 + ((g >> 1) << 3) + rr;
                uint32_t off = swz16(brow, kt * 2 + (g & 1));
                uint32_t x0, x1, x2, x3;
                ldsm4(x0, x1, x2, x3, sb + x_b + off);
                mma16816h(o[2 * np],     pa, x0, x1);
                mma16816h(o[2 * np + 1], pa, x2, x3);
            }
        }
        rs0 += __shfl_xor_sync(0xffffffffu, rs0, 1);
        rs0 += __shfl_xor_sync(0xffffffffu, rs0, 2);
        rs1 += __shfl_xor_sync(0xffffffffu, rs1, 1);
        rs1 += __shfl_xor_sync(0xffffffffu, rs1, 2);
        lc0 = lc0 * sc0 + rs0;
        lc1 = lc1 * sc1 + rs1;

        // ---- bottom: this iter's buffers fully consumed -> refill with it+2 ----
        __syncthreads();
        if (it + 2 < NITER) {
            int jn = jb0 + (it + 2) * BN;
#pragma unroll
            for (int i = tid; i < 128 * 8; i += 128) {
                int row = i >> 3, ch = i & 7;
                uint32_t sw = swz8(row, ch);
                cpa16(sb + kh_b + sw, g_Kh + (size_t)(jn + row) * DIM + ch * 8);
                cpa16(sb + kl_b + sw, g_Kl + (size_t)(jn + row) * DIM + ch * 8);
            }
#pragma unroll
            for (int i = tid; i < 64 * 16; i += 128) {
                int row = i >> 4, ch = i & 15;
                uint32_t sw = swz16(row, ch);
                cpa16(sb + x_b + sw, g_Xt + (size_t)row * N_TOK + jn + ch * 8);
            }
            CP_COMMIT();
        }
    }

    // ---- epilogue ----
    {
        int q = lane >> 2;
        int cb = (lane & 3) * 2;
        int r_lo = row0 + m0 + q;
        int r_hi = r_lo + 8;
        float* olo = g_Opart[half] + (size_t)r_lo * DIM;
        float* ohi = g_Opart[half] + (size_t)r_hi * DIM;
#pragma unroll
        for (int t = 0; t < 8; t++) {
            olo[t * 8 + cb]     = o[t][0];
            olo[t * 8 + cb + 1] = o[t][1];
            ohi[t * 8 + cb]     = o[t][2];
            ohi[t * 8 + cb + 1] = o[t][3];
        }
        if ((lane & 3) == 0) {
            g_mpart[half][r_lo] = mc0; g_mpart[half][r_hi] = mc1;
            g_lpart[half][r_lo] = lc0; g_lpart[half][r_hi] = lc1;
        }
    }
}

// ---------------- combine ----------------
__global__ __launch_bounds__(256) void combine_kernel(float* __restrict__ out) {
    int idx = blockIdx.x * 256 + threadIdx.x;
    int row = idx >> 6;
    int c = idx & 63;
    float m0 = g_mpart[0][row], m1 = g_mpart[1][row];
    float M = fmaxf(m0, m1);
    float w0 = __expf(m0 - M), w1 = __expf(m1 - M);
    float inv = 1.0f / (g_lpart[0][row] * w0 + g_lpart[1][row] * w1);
    out[(size_t)row * DIM + c] =
        (g_Opart[0][(size_t)row * DIM + c] * w0 + g_Opart[1][(size_t)row * DIM + c] * w1) * inv;
}

extern "C" void kernel_launch(void* const* d_in, const int* in_sizes, int n_in,
                              void* d_out, int out_size) {
    const float* x = (const float*)d_in[0];
    const float* R = (const float*)d_in[1];
    const float* E = (const float*)d_in[2];
    float* out = (float*)d_out;

    cudaFuncSetAttribute(proj_kernel, cudaFuncAttributeMaxDynamicSharedMemorySize, PROJ_SMEM);
    proj_kernel<<<N_TOK / 16, 256, PROJ_SMEM>>>(x, R, E);

    cudaFuncSetAttribute(attn_kernel, cudaFuncAttributeMaxDynamicSharedMemorySize, SMEM_TOTAL);
    attn_kernel<<<(N_TOK / BM) * 2, 128, SMEM_TOTAL>>>();

    combine_kernel<<<(N_TOK * DIM) / 256, 256>>>(out);
}

// round 13
// speedup vs baseline: 1.0740x; 1.0740x over previous
#include <cuda_runtime.h>
#include <cuda_bf16.h>
#include <cuda_fp16.h>
#include <cstdint>

#define N_TOK 8192
#define DIM   64
#define BM    64
#define BN    128
#define HALF_KV 4096
#define NITER (HALF_KV / BN)   // 32

// ---------------- global scratch ----------------
__device__ __nv_bfloat16 g_Qh[N_TOK * DIM], g_Ql[N_TOK * DIM];
__device__ __nv_bfloat16 g_Kh[N_TOK * DIM], g_Kl[N_TOK * DIM];
__device__ __half g_Xt[DIM * N_TOK];
__device__ float g_Opart[2][N_TOK * DIM];
__device__ float g_mpart[2][N_TOK];
__device__ float g_lpart[2][N_TOK];

// ---------------- helpers ----------------
__device__ __forceinline__ uint32_t smem_u32(const void* p) {
    uint32_t a;
    asm("{ .reg .u64 t; cvta.to.shared.u64 t, %1; cvt.u32.u64 %0, t; }" : "=r"(a) : "l"(p));
    return a;
}
__device__ __forceinline__ uint32_t swz8(uint32_t row, uint32_t ch) {
    return row * 128u + ((ch ^ (row & 7u)) << 4);
}
__device__ __forceinline__ uint32_t swz16(uint32_t row, uint32_t ch) {
    return row * 256u + ((ch ^ (row & 7u)) << 4);
}
__device__ __forceinline__ void ldsm4(uint32_t& r0, uint32_t& r1, uint32_t& r2,
                                      uint32_t& r3, uint32_t addr) {
    asm volatile("ldmatrix.sync.aligned.m8n8.x4.shared.b16 {%0,%1,%2,%3}, [%4];"
                 : "=r"(r0), "=r"(r1), "=r"(r2), "=r"(r3) : "r"(addr));
}
__device__ __forceinline__ void mma16816(float* c, const uint32_t* a, uint32_t b0,
                                         uint32_t b1) {
    asm volatile(
        "mma.sync.aligned.m16n8k16.row.col.f32.bf16.bf16.f32 "
        "{%0,%1,%2,%3}, {%4,%5,%6,%7}, {%8,%9}, {%0,%1,%2,%3};"
        : "+f"(c[0]), "+f"(c[1]), "+f"(c[2]), "+f"(c[3])
        : "r"(a[0]), "r"(a[1]), "r"(a[2]), "r"(a[3]), "r"(b0), "r"(b1));
}
__device__ __forceinline__ void mma16816h(float* c, const uint32_t* a, uint32_t b0,
                                          uint32_t b1) {
    asm volatile(
        "mma.sync.aligned.m16n8k16.row.col.f32.f16.f16.f32 "
        "{%0,%1,%2,%3}, {%4,%5,%6,%7}, {%8,%9}, {%0,%1,%2,%3};"
        : "+f"(c[0]), "+f"(c[1]), "+f"(c[2]), "+f"(c[3])
        : "r"(a[0]), "r"(a[1]), "r"(a[2]), "r"(a[3]), "r"(b0), "r"(b1));
}
__device__ __forceinline__ uint32_t cvt2h(float lo, float hi) {
    uint32_t r;
    asm("cvt.rn.f16x2.f32 %0, %1, %2;" : "=r"(r) : "f"(hi), "f"(lo));
    return r;
}
// packed fp16x2 exp2
__device__ __forceinline__ uint32_t ex2h2(uint32_t v) {
    uint32_t r;
    asm("ex2.approx.f16x2 %0, %1;" : "=r"(r) : "r"(v));
    return r;
}
__device__ __forceinline__ void cpa16(uint32_t dst, const void* src) {
    asm volatile("cp.async.cg.shared.global [%0], [%1], 16;" :: "r"(dst), "l"(src));
}
#define CP_COMMIT() asm volatile("cp.async.commit_group;" ::: "memory")
#define CP_WAIT(n)  asm volatile("cp.async.wait_group %0;" :: "n"(n) : "memory")
#define ONES_H2 0x3C003C00u

// Q pre-scale: log2(e) / sqrt(64)  -> logits in log2 domain
#define QSCALE 0.18033688011112042f

// ---------------- projection + split kernel (R11 config: 256 blocks x 32 rows) ----------------
__global__ __launch_bounds__(256) void proj_kernel(const float* __restrict__ x,
                                                   const float* __restrict__ R,
                                                   const float* __restrict__ E) {
    extern __shared__ float psm[];
    float* Rs = psm;                 // 4096
    float* Es = psm + 4096;          // 4096
    float* xs = psm + 8192;          // 32*65 padded
    int tid = threadIdx.x;
    int row0 = blockIdx.x * 32;
    {
        const float4* Rsrc = (const float4*)R;
        const float4* Esrc = (const float4*)E;
        float4* Rd = (float4*)Rs;
        float4* Ed = (float4*)Es;
#pragma unroll
        for (int i = tid; i < 1024; i += 256) { Rd[i] = Rsrc[i]; Ed[i] = Esrc[i]; }
    }
#pragma unroll
    for (int i = tid; i < 2048; i += 256) {
        int row = i >> 6, c = i & 63;
        xs[row * 65 + c] = x[(size_t)(row0 + row) * 64 + c];
    }
    __syncthreads();

    // coalesced transposed fp16 store of x
#pragma unroll
    for (int i = tid; i < 2048; i += 256) {
        int d = i >> 5, row = i & 31;
        g_Xt[(size_t)d * N_TOK + row0 + row] = __float2half_rn(xs[row * 65 + d]);
    }

    int ty = tid >> 6, col = tid & 63;
    float aq[8], ak[8];
#pragma unroll
    for (int r = 0; r < 8; r++) { aq[r] = 0.f; ak[r] = 0.f; }
#pragma unroll 8
    for (int k = 0; k < 64; k++) {
        float rv = Rs[k * 64 + col];
        float ev = Es[k * 64 + col];
#pragma unroll
        for (int r = 0; r < 8; r++) {
            float xv = xs[(r * 4 + ty) * 65 + k];
            aq[r] = fmaf(xv, rv, aq[r]);
            ak[r] = fmaf(xv, ev, ak[r]);
        }
    }
#pragma unroll
    for (int r = 0; r < 8; r++) {
        int row = row0 + r * 4 + ty;
        float q = aq[r] * QSCALE;
        __nv_bfloat16 qh = __float2bfloat16(q);
        g_Qh[(size_t)row * 64 + col] = qh;
        g_Ql[(size_t)row * 64 + col] = __float2bfloat16(q - __bfloat162float(qh));
        __nv_bfloat16 kh = __float2bfloat16(ak[r]);
        g_Kh[(size_t)row * 64 + col] = kh;
        g_Kl[(size_t)row * 64 + col] = __float2bfloat16(ak[r] - __bfloat162float(kh));
    }
}
#define PROJ_SMEM ((4096 + 4096 + 32 * 65) * 4)

// ---------------- fused flash attention (R11 pipeline + log2/f16x2 softmax) ----------------
#define OFF_KH0 0
#define OFF_KL0 16384
#define OFF_KH1 32768
#define OFF_KL1 49152
#define OFF_X   65536
#define SMEM_TOTAL 81920

__global__ __launch_bounds__(128, 2) void attn_kernel() {
    extern __shared__ char sm[];
    uint32_t sb = smem_u32(sm);
    const int tid = threadIdx.x;
    const int lane = tid & 31;
    const int w = tid >> 5;
    const int m0 = w * 16;
    const int rb = blockIdx.x >> 1;
    const int half = blockIdx.x & 1;
    const int row0 = rb * BM;
    const int jb0 = half * HALF_KV;
    const int g = lane >> 3, rr = lane & 7;

    // ---- stage Q (hi/lo) into X smem region (8KB each), build A-fragments once ----
#pragma unroll
    for (int i = tid; i < 64 * 8; i += 128) {
        int row = i >> 3, ch = i & 7;
        uint32_t sw = swz8(row, ch);
        *(uint4*)(sm + OFF_X + sw) = *(const uint4*)(g_Qh + (size_t)(row0 + row) * DIM + ch * 8);
        *(uint4*)(sm + OFF_X + 8192 + sw) = *(const uint4*)(g_Ql + (size_t)(row0 + row) * DIM + ch * 8);
    }
    __syncthreads();

    uint32_t qh[4][4], ql[4][4];
    {
        int arow = m0 + ((g & 1) << 3) + rr;
#pragma unroll
        for (int ks = 0; ks < 4; ks++) {
            uint32_t off = swz8(arow, ks * 2 + (g >> 1));
            ldsm4(qh[ks][0], qh[ks][1], qh[ks][2], qh[ks][3], sb + OFF_X + off);
            ldsm4(ql[ks][0], ql[ks][1], ql[ks][2], ql[ks][3], sb + OFF_X + 8192 + off);
        }
    }
    __syncthreads();   // Q frags built; X region reusable

    // ---- prologue: issue K(0) into buffer 0 ----
#pragma unroll
    for (int i = tid; i < 128 * 8; i += 128) {
        int row = i >> 3, ch = i & 7;
        uint32_t sw = swz8(row, ch);
        cpa16(sb + OFF_KH0 + sw, g_Kh + (size_t)(jb0 + row) * DIM + ch * 8);
        cpa16(sb + OFF_KL0 + sw, g_Kl + (size_t)(jb0 + row) * DIM + ch * 8);
    }
    CP_COMMIT();

    float o[8][4];
#pragma unroll
    for (int t = 0; t < 8; t++)
#pragma unroll
        for (int j = 0; j < 4; j++) o[t][j] = 0.f;
    float os[4];                       // ones-column accumulator (row sums l)
#pragma unroll
    for (int j = 0; j < 4; j++) os[j] = 0.f;
    float mc0 = -3.0e38f, mc1 = -3.0e38f;

    for (int it = 0; it < NITER; it++) {
        int jb = jb0 + it * BN;
        __syncthreads();   // X buffer + K[(it+1)&1] free

        // ---- issue X(it): 64 d-rows x 128 tokens fp16 ----
#pragma unroll
        for (int i = tid; i < 64 * 16; i += 128) {
            int row = i >> 4, ch = i & 15;
            uint32_t sw = swz16(row, ch);
            cpa16(sb + OFF_X + sw, g_Xt + (size_t)row * N_TOK + jb + ch * 8);
        }
        CP_COMMIT();
        // ---- issue K(it+1) ----
        if (it + 1 < NITER) {
            uint32_t kb_h = ((it + 1) & 1) ? OFF_KH1 : OFF_KH0;
            uint32_t kb_l = ((it + 1) & 1) ? OFF_KL1 : OFF_KL0;
            int jn = jb + BN;
#pragma unroll
            for (int i = tid; i < 128 * 8; i += 128) {
                int row = i >> 3, ch = i & 7;
                uint32_t sw = swz8(row, ch);
                cpa16(sb + kb_h + sw, g_Kh + (size_t)(jn + row) * DIM + ch * 8);
                cpa16(sb + kb_l + sw, g_Kl + (size_t)(jn + row) * DIM + ch * 8);
            }
            CP_COMMIT();
            CP_WAIT(2);    // K(it) done
        } else {
            CP_WAIT(1);    // K(it) done
        }
        __syncthreads();   // K(it) visible

        uint32_t kh_b = (it & 1) ? OFF_KH1 : OFF_KH0;
        uint32_t kl_b = (it & 1) ? OFF_KL1 : OFF_KL0;

        // ---- GEMM1: S = Qh*Kh + Qh*Kl + Ql*Kh (bf16 3-pass, log2-domain) ----
        float s[16][4];
#pragma unroll
        for (int t = 0; t < 16; t++)
#pragma unroll
            for (int j = 0; j < 4; j++) s[t][j] = 0.f;
#pragma unroll
        for (int np = 0; np < 8; np++) {
            int brow = np * 16 + ((g >> 1) << 3) + rr;
#pragma unroll
            for (int ks = 0; ks < 4; ks++) {
                uint32_t off = swz8(brow, ks * 2 + (g & 1));
                uint32_t b0, b1, b2, b3, c0, c1, c2, c3;
                ldsm4(b0, b1, b2, b3, sb + kh_b + off);
                ldsm4(c0, c1, c2, c3, sb + kl_b + off);
                mma16816(s[2 * np],     qh[ks], b0, b1);
                mma16816(s[2 * np + 1], qh[ks], b2, b3);
                mma16816(s[2 * np],     qh[ks], c0, c1);
                mma16816(s[2 * np + 1], qh[ks], c2, c3);
                mma16816(s[2 * np],     ql[ks], b0, b1);
                mma16816(s[2 * np + 1], ql[ks], b2, b3);
            }
        }

        // ---- X(it) visible before the interleaved region ----
        if (it + 1 < NITER) { CP_WAIT(1); } else { CP_WAIT(0); }
        __syncthreads();

        // ---- row max (log2 domain) ----
        float mx0 = -3.0e38f, mx1 = -3.0e38f;
#pragma unroll
        for (int t = 0; t < 16; t++) {
            mx0 = fmaxf(mx0, fmaxf(s[t][0], s[t][1]));
            mx1 = fmaxf(mx1, fmaxf(s[t][2], s[t][3]));
        }
        mx0 = fmaxf(mx0, __shfl_xor_sync(0xffffffffu, mx0, 1));
        mx0 = fmaxf(mx0, __shfl_xor_sync(0xffffffffu, mx0, 2));
        mx1 = fmaxf(mx1, __shfl_xor_sync(0xffffffffu, mx1, 1));
        mx1 = fmaxf(mx1, __shfl_xor_sync(0xffffffffu, mx1, 2));
        float mn0 = fmaxf(mc0, mx0), mn1 = fmaxf(mc1, mx1);
        float sc0 = exp2f(mc0 - mn0), sc1 = exp2f(mc1 - mn1);
        mc0 = mn0; mc1 = mn1;

        // ---- rescale O and row-sum accumulators ----
#pragma unroll
        for (int t = 0; t < 8; t++) {
            o[t][0] *= sc0; o[t][1] *= sc0;
            o[t][2] *= sc1; o[t][3] *= sc1;
        }
        os[0] *= sc0; os[1] *= sc0; os[2] *= sc1; os[3] *= sc1;

        // ---- interleaved: pack+ex2 chunk kt, ones-MMA (row sum), then GEMM2 ----
#pragma unroll
        for (int kt = 0; kt < 8; kt++) {
            uint32_t pa[4];
            pa[0] = ex2h2(cvt2h(s[2 * kt][0] - mn0,     s[2 * kt][1] - mn0));
            pa[1] = ex2h2(cvt2h(s[2 * kt][2] - mn1,     s[2 * kt][3] - mn1));
            pa[2] = ex2h2(cvt2h(s[2 * kt + 1][0] - mn0, s[2 * kt + 1][1] - mn0));
            pa[3] = ex2h2(cvt2h(s[2 * kt + 1][2] - mn1, s[2 * kt + 1][3] - mn1));
            mma16816h(os, pa, ONES_H2, ONES_H2);   // row sums -> l
#pragma unroll
            for (int np = 0; np < 4; np++) {
                int brow = np * 16 + ((g >> 1) << 3) + rr;
                uint32_t off = swz16(brow, kt * 2 + (g & 1));
                uint32_t x0, x1, x2, x3;
                ldsm4(x0, x1, x2, x3, sb + OFF_X + off);
                mma16816h(o[2 * np],     pa, x0, x1);
                mma16816h(o[2 * np + 1], pa, x2, x3);
            }
        }
    }

    // ---- epilogue ----
    {
        int q = lane >> 2;
        int cb = (lane & 3) * 2;
        int r_lo = row0 + m0 + q;
        int r_hi = r_lo + 8;
        float* olo = g_Opart[half] + (size_t)r_lo * DIM;
        float* ohi = g_Opart[half] + (size_t)r_hi * DIM;
#pragma unroll
        for (int t = 0; t < 8; t++) {
            olo[t * 8 + cb]     = o[t][0];
            olo[t * 8 + cb + 1] = o[t][1];
            ohi[t * 8 + cb]     = o[t][2];
            ohi[t * 8 + cb + 1] = o[t][3];
        }
        if ((lane & 3) == 0) {
            g_mpart[half][r_lo] = mc0; g_mpart[half][r_hi] = mc1;
            g_lpart[half][r_lo] = os[0]; g_lpart[half][r_hi] = os[2];
        }
    }
}

// ---------------- combine (log2-domain m) ----------------
__global__ __launch_bounds__(256) void combine_kernel(float* __restrict__ out) {
    int idx = blockIdx.x * 256 + threadIdx.x;
    int row = idx >> 6;
    int c = idx & 63;
    float m0 = g_mpart[0][row], m1 = g_mpart[1][row];
    float M = fmaxf(m0, m1);
    float w0 = exp2f(m0 - M), w1 = exp2f(m1 - M);
    float inv = 1.0f / (g_lpart[0][row] * w0 + g_lpart[1][row] * w1);
    out[(size_t)row * DIM + c] =
        (g_Opart[0][(size_t)row * DIM + c] * w0 + g_Opart[1][(size_t)row * DIM + c] * w1) * inv;
}

extern "C" void kernel_launch(void* const* d_in, const int* in_sizes, int n_in,
                              void* d_out, int out_size) {
    const float* x = (const float*)d_in[0];
    const float* R = (const float*)d_in[1];
    const float* E = (const float*)d_in[2];
    float* out = (float*)d_out;

    cudaFuncSetAttribute(proj_kernel, cudaFuncAttributeMaxDynamicSharedMemorySize, PROJ_SMEM);
    proj_kernel<<<N_TOK / 32, 256, PROJ_SMEM>>>(x, R, E);

    cudaFuncSetAttribute(attn_kernel, cudaFuncAttributeMaxDynamicSharedMemorySize, SMEM_TOTAL);
    attn_kernel<<<(N_TOK / BM) * 2, 128, SMEM_TOTAL>>>();

    combine_kernel<<<(N_TOK * DIM) / 256, 256>>>(out);
}